// round 12
// baseline (speedup 1.0000x reference)
#include <cuda_runtime.h>
#include <math.h>

// ---------------------------------------------------------------------------
// CReST loss, 6 kernels on 2 streams (graph fork/join via events):
//   main: k_wu -> k_seghist_rank -> k_scan -> k_compact -> k_su -> k_reduce
//   side: k_x (independent; overlaps the latency-bound small-kernel chain)
//   out[0]=loss, out[1]=Lx, out[2]=Lu, out[3..3+N)=max_probs
// ---------------------------------------------------------------------------

#define FULLMASK 0xffffffffu
#define MAXC 1024
#define SEG 256
#define MAXN 65536
#define NSEG_MAX (MAXN / SEG)
#define MAXBX 32768
#define WPB 8
#define L2E 1.4426950408889634f

__device__ int           g_tm[MAXN];
__device__ unsigned char g_local[MAXN];
__device__ float         g_ce_x[MAXBX];
__device__ float         g_ce_u[MAXN];
__device__ int           g_seg_counts_t[MAXC][NSEG_MAX];  // [class][segment]
__device__ int           g_thr[NSEG_MAX][MAXC];  // bn[c] - seg_off[s][c]
__device__ int           g_alist[MAXN];          // active rows for k_su
__device__ unsigned int  g_nact = 0;             // reset by k_scan

// ---- k_wu: weak-aug rows -> max_probs + pseudo target -----------------------
__global__ void __launch_bounds__(WPB * 32, 8)
k_wu(const float* __restrict__ lwu, int C, int N,
     float* __restrict__ maxp_out) {
    int lane = threadIdx.x & 31;
    int row = blockIdx.x * WPB + (threadIdx.x >> 5);
    if (row >= N) return;
    int n4 = C >> 2;
    int tail = C & 3;

    const float* rowp = lwu + (size_t)row * C;
    const float4* rp = (const float4*)rowp;

    float m = -INFINITY;
    int bi = 0x3fffffff;
    float s0 = 0.f, s1 = 0.f;
    #pragma unroll
    for (int u = 0; u < 8; u++) {
        int k = lane + u * 32;
        if (k < n4) {
            float4 c = __ldcs(rp + k);
            int j = 4 * k;
            if (c.x > m) { m = c.x; bi = j; }
            if (c.y > m) { m = c.y; bi = j + 1; }
            if (c.z > m) { m = c.z; bi = j + 2; }
            if (c.w > m) { m = c.w; bi = j + 3; }
            s0 += exp2f(c.x * L2E) + exp2f(c.y * L2E);
            s1 += exp2f(c.z * L2E) + exp2f(c.w * L2E);
        }
    }
    if (tail && lane < tail) {
        int j = 4 * n4 + lane;
        float tv = __ldcs(rowp + j);
        if (tv > m) { m = tv; bi = j; }
        s0 += exp2f(tv * L2E);
    }
    float s = s0 + s1;

    #pragma unroll
    for (int o = 16; o; o >>= 1) {
        float om = __shfl_xor_sync(FULLMASK, m, o);
        int   oi = __shfl_xor_sync(FULLMASK, bi, o);
        s += __shfl_xor_sync(FULLMASK, s, o);
        if (om > m || (om == m && oi < bi)) { m = om; bi = oi; }
    }

    if (lane == 0) {
        float maxp = exp2f(m * L2E) / s;
        maxp_out[row] = maxp;
        g_tm[row] = (maxp >= 0.95f) ? bi : 0;
    }
}

// ---- k_x: supervised CE per row (independent; runs on side stream) ----------
__global__ void __launch_bounds__(WPB * 32, 8)
k_x(const float* __restrict__ lx, int C, int Bx,
    const int* __restrict__ tgts) {
    int lane = threadIdx.x & 31;
    int row = blockIdx.x * WPB + (threadIdx.x >> 5);
    if (row >= Bx) return;
    int n4 = C >> 2;
    int tail = C & 3;

    const float* rowp = lx + (size_t)row * C;
    const float4* rp = (const float4*)rowp;
    float tval = __ldg(rowp + tgts[row]);

    float s0 = 0.f, s1 = 0.f;
    #pragma unroll
    for (int u = 0; u < 8; u++) {
        int k = lane + u * 32;
        if (k < n4) {
            float4 c = __ldcs(rp + k);
            s0 += exp2f(c.x * L2E) + exp2f(c.y * L2E);
            s1 += exp2f(c.z * L2E) + exp2f(c.w * L2E);
        }
    }
    if (tail && lane < tail)
        s0 += exp2f(__ldcs(rowp + 4 * n4 + lane) * L2E);
    float s = s0 + s1;

    #pragma unroll
    for (int o = 16; o; o >>= 1) s += __shfl_xor_sync(FULLMASK, s, o);

    if (lane == 0)
        g_ce_x[row] = logf(s) - tval;
}

// ---- k_seghist_rank: per-segment class counts (transposed) + stable rank ----
__global__ void k_seghist_rank(int N, int C) {
    __shared__ unsigned char whist[WPB][MAXC];
    int r = threadIdx.x;
    int w = r >> 5;
    int lane = r & 31;
    int row = blockIdx.x * SEG + r;

    unsigned int* hz = (unsigned int*)whist;
    #pragma unroll
    for (int i = r; i < WPB * MAXC / 4; i += SEG) hz[i] = 0u;

    int myc = (row < N) ? g_tm[row] : -1;

    unsigned int mmask = __match_any_sync(FULLMASK, myc);
    int within = __popc(mmask & ((1u << lane) - 1u));
    int leader = __ffs(mmask) - 1;

    __syncthreads();
    if (lane == leader && myc >= 0)
        whist[w][myc] = (unsigned char)__popc(mmask);
    __syncthreads();

    if (row < N) {
        int cross = 0;
        #pragma unroll
        for (int j = 0; j < WPB; j++)
            if (j < w) cross += whist[j][myc];
        g_local[row] = (unsigned char)(cross + within);
    }

    // transposed store: scattered writes, coalesced scan reads
    for (int c = r; c < C; c += SEG) {
        int cnt = 0;
        #pragma unroll
        for (int j = 0; j < WPB; j++) cnt += whist[j][c];
        g_seg_counts_t[c][blockIdx.x] = cnt;
    }
}

// ---- k_scan: per-class scan over segments, write thresholds -----------------
__global__ void k_scan(int nseg, const float* __restrict__ gtp) {
    int c = blockIdx.x;
    int s = threadIdx.x;
    int lane = s & 31, w = s >> 5;

    if (c == 0 && s == 0) g_nact = 0;    // reset before k_compact fills it

    int v = (s < nseg) ? g_seg_counts_t[c][s] : 0;   // coalesced

    int x = v;
    #pragma unroll
    for (int o = 1; o < 32; o <<= 1) {
        int t = __shfl_up_sync(FULLMASK, x, o);
        if (lane >= o) x += t;
    }

    __shared__ int wsum[8];
    __shared__ int woff[8];
    __shared__ int tot;
    if (lane == 31) wsum[w] = x;
    __syncthreads();
    if (w == 0) {
        int y = (lane < 8) ? wsum[lane] : 0;
        #pragma unroll
        for (int o = 1; o < 8; o <<= 1) {
            int t = __shfl_up_sync(FULLMASK, y, o);
            if (lane >= o) y += t;
        }
        if (lane < 8) woff[lane] = y;
    }
    __syncthreads();

    int incl = x + (w ? woff[w - 1] : 0);
    if (s == SEG - 1) tot = incl;         // total count of class c
    __syncthreads();

    if (s < nseg) {
        // bn = round-half-even(total * gtp[c]), matching jnp.round
        int bn = (int)rintf((float)tot * gtp[c]);
        g_thr[s][c] = bn - (incl - v);    // bn - exclusive_offset
    }
}

// ---- k_compact: build active-row list (single gather) -----------------------
__global__ void k_compact(int N) {
    int row = blockIdx.x * SEG + threadIdx.x;
    if (row >= N) return;
    int tgt = g_tm[row];
    bool active = false;
    if (tgt != 0)
        active = ((int)g_local[row] < g_thr[row >> 8][tgt]);
    if (active) {
        unsigned int p = atomicAdd(&g_nact, 1u);
        g_alist[p] = row;
    } else {
        g_ce_u[row] = 0.f;
    }
}

// ---- k_su: unsupervised CE for active rows only -----------------------------
__global__ void __launch_bounds__(WPB * 32, 8)
k_su(const float* __restrict__ lsu, int C) {
    int lane = threadIdx.x & 31;
    int w = blockIdx.x * WPB + (threadIdx.x >> 5);
    if (w >= (int)g_nact) return;        // one broadcast load, then exit
    int row = g_alist[w];
    int tgt = g_tm[row];

    const float* rowp = lsu + (size_t)row * C;
    const float4* rp = (const float4*)rowp;
    int n4 = C >> 2;
    int tail = C & 3;
    float tval = __ldg(rowp + tgt);

    float s0 = 0.f, s1 = 0.f;
    #pragma unroll
    for (int u = 0; u < 8; u++) {
        int k = lane + u * 32;
        if (k < n4) {
            float4 c = __ldcs(rp + k);
            s0 += exp2f(c.x * L2E) + exp2f(c.y * L2E);
            s1 += exp2f(c.z * L2E) + exp2f(c.w * L2E);
        }
    }
    if (tail && lane < tail)
        s0 += exp2f(__ldcs(rowp + 4 * n4 + lane) * L2E);
    float s = s0 + s1;

    #pragma unroll
    for (int o = 16; o; o >>= 1) s += __shfl_xor_sync(FULLMASK, s, o);

    if (lane == 0)
        g_ce_u[row] = logf(s) - tval;
}

// ---- k_reduce: deterministic final reduction --------------------------------
__global__ void k_reduce(int Bx, int N, float* __restrict__ out) {
    __shared__ float sh[1024];
    __shared__ float lx_s;
    int tid = threadIdx.x;

    float a = 0.f;
    for (int i = tid; i < Bx; i += 1024) a += g_ce_x[i];
    sh[tid] = a;
    __syncthreads();
    for (int o = 512; o; o >>= 1) {
        if (tid < o) sh[tid] += sh[tid + o];
        __syncthreads();
    }
    if (tid == 0) lx_s = sh[0];
    __syncthreads();

    float b = 0.f;
    for (int i = tid; i < N; i += 1024) b += g_ce_u[i];
    sh[tid] = b;
    __syncthreads();
    for (int o = 512; o; o >>= 1) {
        if (tid < o) sh[tid] += sh[tid + o];
        __syncthreads();
    }
    if (tid == 0) {
        float Lx = lx_s / (float)Bx;
        float Lu = sh[0] / (float)N;
        out[0] = Lx + Lu;  // LAMBDA_U = 1.0
        out[1] = Lx;
        out[2] = Lu;
    }
}

// ---------------------------------------------------------------------------
extern "C" void kernel_launch(void* const* d_in, const int* in_sizes, int n_in,
                              void* d_out, int out_size) {
    const float* lx  = (const float*)d_in[0];
    const float* lwu = (const float*)d_in[1];
    const float* lsu = (const float*)d_in[2];
    const int*   tx  = (const int*)d_in[3];
    const float* gtp = (const float*)d_in[4];
    // d_in[5] = t (unused)

    int Bx = in_sizes[3];
    int C  = in_sizes[4];
    int N  = in_sizes[1] / C;
    int nseg = (N + SEG - 1) / SEG;

    float* out = (float*)d_out;

    int blk_wu = (N + WPB - 1) / WPB;
    int blk_x  = (Bx + WPB - 1) / WPB;
    int blk_n  = (N + WPB - 1) / WPB;

    // one-time side stream + events (host-side objects, no device memory)
    static cudaStream_t s1 = nullptr;
    static cudaEvent_t efork = nullptr, ejoin = nullptr;
    if (!s1) {
        cudaStreamCreateWithFlags(&s1, cudaStreamNonBlocking);
        cudaEventCreateWithFlags(&efork, cudaEventDisableTiming);
        cudaEventCreateWithFlags(&ejoin, cudaEventDisableTiming);
    }

    // fork: k_x runs on side stream, overlapping the small-kernel chain
    cudaEventRecord(efork, 0);
    cudaStreamWaitEvent(s1, efork, 0);
    k_x<<<blk_x, WPB * 32, 0, s1>>>(lx, C, Bx, tx);
    cudaEventRecord(ejoin, s1);

    // main chain (default stream)
    k_wu<<<blk_wu, WPB * 32>>>(lwu, C, N, out + 3);
    k_seghist_rank<<<nseg, SEG>>>(N, C);
    k_scan<<<C, SEG>>>(nseg, gtp);
    k_compact<<<nseg, SEG>>>(N);
    k_su<<<blk_n, WPB * 32>>>(lsu, C);

    // join, then final reduction
    cudaStreamWaitEvent(0, ejoin, 0);
    k_reduce<<<1, 1024>>>(Bx, N, out);
}